// round 4
// baseline (speedup 1.0000x reference)
#include <cuda_runtime.h>
#include <cstdint>

// ---------------------------------------------------------------------------
// Problem constants (fixed shapes from reference_code)
// ---------------------------------------------------------------------------
#define N_TOK   8192          // S*T tokens
#define M_DIM   2048          // model dim
#define E_NUM   8             // experts
#define H_DIM   8192          // FFN hidden
#define C_CAP   1024          // capacity per expert
#define EC_SLOTS 8192         // E * C

// ---------------------------------------------------------------------------
// Scratch (device globals; no dynamic allocation allowed)
// ---------------------------------------------------------------------------
__device__ int   g_idx  [N_TOK];                 // argmax expert per token
__device__ float g_gate1[N_TOK];                 // top-1 gate value per token
__device__ float g_gates[N_TOK * E_NUM];         // full softmax (for l_aux me)
__device__ int   g_s2t  [EC_SLOTS];              // slot -> token (-1 empty)
__device__ float g_h    [(size_t)EC_SLOTS * H_DIM];  // 256 MB FFN hidden

// ---------------------------------------------------------------------------
// init: slot table to -1, zero the output tensor region
// ---------------------------------------------------------------------------
__global__ void init_kernel(float* __restrict__ out)
{
    int tid = blockIdx.x * blockDim.x + threadIdx.x;
    if (tid < EC_SLOTS) g_s2t[tid] = -1;
    float4* o4 = (float4*)out;
    const int n4 = (N_TOK * M_DIM) / 4;
    const int stride = gridDim.x * blockDim.x;
    for (int i = tid; i < n4; i += stride)
        o4[i] = make_float4(0.f, 0.f, 0.f, 0.f);
}

// ---------------------------------------------------------------------------
// gate: per-token logits (8 dots of length 2048), softmax, argmax
// one block per token; warp w computes expert w's logit
// ---------------------------------------------------------------------------
__global__ __launch_bounds__(256) void gate_kernel(
    const float* __restrict__ x,
    const float* __restrict__ wg)
{
    __shared__ float sx[M_DIM];
    __shared__ float slog[E_NUM];

    const int tok = blockIdx.x;
    const int tid = threadIdx.x;

    // stage token row into smem (vectorized)
    const float4* xr = (const float4*)(x + (size_t)tok * M_DIM);
    float4* sx4 = (float4*)sx;
    for (int i = tid; i < M_DIM / 4; i += 256) sx4[i] = xr[i];
    __syncthreads();

    const int wid = tid >> 5, lane = tid & 31;
    const float* __restrict__ w = wg + wid * M_DIM;
    float sum = 0.f;
    for (int m = lane; m < M_DIM; m += 32) sum = fmaf(sx[m], w[m], sum);
#pragma unroll
    for (int o = 16; o; o >>= 1) sum += __shfl_xor_sync(0xffffffffu, sum, o);
    if (lane == 0) slog[wid] = sum;
    __syncthreads();

    if (tid == 0) {
        float mx = slog[0]; int am = 0;
#pragma unroll
        for (int e = 1; e < E_NUM; ++e)
            if (slog[e] > mx) { mx = slog[e]; am = e; }   // first-max, matches jnp.argmax
        float ge[E_NUM], den = 0.f;
#pragma unroll
        for (int e = 0; e < E_NUM; ++e) { ge[e] = __expf(slog[e] - mx); den += ge[e]; }
        // use precise exp for safety with the 1e-3 gate-weight path
        den = 0.f;
#pragma unroll
        for (int e = 0; e < E_NUM; ++e) { ge[e] = expf(slog[e] - mx); den += ge[e]; }
        const float inv = 1.f / den;
#pragma unroll
        for (int e = 0; e < E_NUM; ++e) g_gates[tok * E_NUM + e] = ge[e] * inv;
        g_idx[tok]   = am;
        g_gate1[tok] = ge[am] * inv;
    }
}

// ---------------------------------------------------------------------------
// sched: order-preserving capacity assignment (exact cumsum semantics),
// plus l_aux = sum(me*ce) * E / N^2 written to out[N*M] when requested.
// single block, warp e owns expert e.
// ---------------------------------------------------------------------------
__global__ __launch_bounds__(256) void sched_kernel(float* __restrict__ out,
                                                    int write_laux)
{
    __shared__ int   s_ce[E_NUM];
    __shared__ float s_me[E_NUM];

    const int tid = threadIdx.x;
    const int wid = tid >> 5, lane = tid & 31;

    int count = 0;
    for (int base = 0; base < N_TOK; base += 32) {
        const int tok = base + lane;
        const bool mine = (g_idx[tok] == wid);
        const unsigned bal = __ballot_sync(0xffffffffu, mine);
        if (mine) {
            const int loc = count + __popc(bal & ((1u << lane) - 1u));
            if (loc < C_CAP) g_s2t[wid * C_CAP + loc] = tok;
        }
        count += __popc(bal);
    }
    if (lane == 0) s_ce[wid] = count;

    // me[e] = sum over tokens of softmax gate for expert e
    float me = 0.f;
    for (int t = lane; t < N_TOK; t += 32) me += g_gates[t * E_NUM + wid];
#pragma unroll
    for (int o = 16; o; o >>= 1) me += __shfl_xor_sync(0xffffffffu, me, o);
    if (lane == 0) s_me[wid] = me;
    __syncthreads();

    if (tid == 0 && write_laux) {
        float acc = 0.f;
#pragma unroll
        for (int e = 0; e < E_NUM; ++e) acc += s_me[e] * (float)s_ce[e];
        out[(size_t)N_TOK * M_DIM] =
            acc * ((float)E_NUM / ((float)N_TOK * (float)N_TOK));
    }
}

// ---------------------------------------------------------------------------
// GEMM1: h[slot, :] = relu( x[token(slot), :] @ w1[e] + b1[e] )
//   A: gathered x rows [EC, M]   B: w1[e] [M, H] row-major   C: g_h [EC, H]
// 128x128 tile, 8x8 per thread, BK=8, register-prefetch double buffering.
// ---------------------------------------------------------------------------
__global__ __launch_bounds__(256) void gemm1_kernel(
    const float* __restrict__ x,
    const float* __restrict__ w1,
    const float* __restrict__ b1)
{
    __shared__ float As[8][128];
    __shared__ float Bs[8][128];
    __shared__ const float* srow[128];

    const int tid  = threadIdx.x;
    const int row0 = blockIdx.y * 128;
    const int col0 = blockIdx.x * 128;
    const int e    = row0 / C_CAP;                    // 128-row tile never crosses experts
    const float* __restrict__ Bg = w1 + (size_t)e * M_DIM * H_DIM;

    if (tid < 128) {
        const int t = g_s2t[row0 + tid];
        srow[tid] = (t >= 0) ? (x + (size_t)t * M_DIM) : (const float*)nullptr;
    }
    __syncthreads();

    const int aRow = tid >> 1;
    const int aCol = (tid & 1) << 2;
    const int bRow = tid >> 5;
    const int bCol = (tid & 31) << 2;
    const int tx = tid & 15;
    const int ty = tid >> 4;

    const float* arp = srow[aRow];

    float acc[8][8];
#pragma unroll
    for (int i = 0; i < 8; ++i)
#pragma unroll
        for (int j = 0; j < 8; ++j) acc[i][j] = 0.f;

    float4 av = arp ? *(const float4*)(arp + aCol)
                    : make_float4(0.f, 0.f, 0.f, 0.f);
    float4 bv = *(const float4*)(Bg + (size_t)bRow * H_DIM + col0 + bCol);

#pragma unroll 1
    for (int k0 = 0; k0 < M_DIM; k0 += 8) {
        As[aCol + 0][aRow] = av.x;
        As[aCol + 1][aRow] = av.y;
        As[aCol + 2][aRow] = av.z;
        As[aCol + 3][aRow] = av.w;
        *(float4*)(&Bs[bRow][bCol]) = bv;
        __syncthreads();

        const int kn = k0 + 8;
        if (kn < M_DIM) {
            av = arp ? *(const float4*)(arp + kn + aCol)
                     : make_float4(0.f, 0.f, 0.f, 0.f);
            bv = *(const float4*)(Bg + (size_t)(kn + bRow) * H_DIM + col0 + bCol);
        }

#pragma unroll
        for (int k = 0; k < 8; ++k) {
            float ra[8], rb[8];
            *(float4*)&ra[0] = *(const float4*)&As[k][ty * 4];
            *(float4*)&ra[4] = *(const float4*)&As[k][ty * 4 + 64];
            *(float4*)&rb[0] = *(const float4*)&Bs[k][tx * 4];
            *(float4*)&rb[4] = *(const float4*)&Bs[k][tx * 4 + 64];
#pragma unroll
            for (int i = 0; i < 8; ++i)
#pragma unroll
                for (int j = 0; j < 8; ++j)
                    acc[i][j] = fmaf(ra[i], rb[j], acc[i][j]);
        }
        __syncthreads();
    }

    const float* b1e = b1 + e * H_DIM + col0;
    float bcol[8];
#pragma unroll
    for (int j = 0; j < 8; ++j) {
        const int c = (j < 4) ? (tx * 4 + j) : (64 + tx * 4 + (j - 4));
        bcol[j] = b1e[c];
    }
#pragma unroll
    for (int i = 0; i < 8; ++i) {
        const int r = row0 + ((i < 4) ? (ty * 4 + i) : (64 + ty * 4 + (i - 4)));
        float* hp = g_h + (size_t)r * H_DIM + col0;
        float4 v0, v1;
        v0.x = fmaxf(acc[i][0] + bcol[0], 0.f);
        v0.y = fmaxf(acc[i][1] + bcol[1], 0.f);
        v0.z = fmaxf(acc[i][2] + bcol[2], 0.f);
        v0.w = fmaxf(acc[i][3] + bcol[3], 0.f);
        v1.x = fmaxf(acc[i][4] + bcol[4], 0.f);
        v1.y = fmaxf(acc[i][5] + bcol[5], 0.f);
        v1.z = fmaxf(acc[i][6] + bcol[6], 0.f);
        v1.w = fmaxf(acc[i][7] + bcol[7], 0.f);
        *(float4*)(hp + tx * 4)      = v0;
        *(float4*)(hp + 64 + tx * 4) = v1;
    }
}

// ---------------------------------------------------------------------------
// GEMM2: out[token(slot), :] = gate1(token) * ( h[slot, :] @ w2[e] + b2[e] )
// fused combine/scatter epilogue; empty slots skipped (out pre-zeroed).
// ---------------------------------------------------------------------------
__global__ __launch_bounds__(256) void gemm2_kernel(
    const float* __restrict__ w2,
    const float* __restrict__ b2,
    float* __restrict__ out)
{
    __shared__ float As[8][128];
    __shared__ float Bs[8][128];
    __shared__ int   stok[128];
    __shared__ float sg[128];

    const int tid  = threadIdx.x;
    const int row0 = blockIdx.y * 128;
    const int col0 = blockIdx.x * 128;
    const int e    = row0 / C_CAP;
    const float* __restrict__ Bg = w2 + (size_t)e * H_DIM * M_DIM;

    if (tid < 128) {
        const int t = g_s2t[row0 + tid];
        stok[tid] = t;
        sg[tid]   = (t >= 0) ? g_gate1[t] : 0.f;
    }
    __syncthreads();

    const int aRow = tid >> 1;
    const int aCol = (tid & 1) << 2;
    const int bRow = tid >> 5;
    const int bCol = (tid & 31) << 2;
    const int tx = tid & 15;
    const int ty = tid >> 4;

    const float* arp = g_h + (size_t)(row0 + aRow) * H_DIM;

    float acc[8][8];
#pragma unroll
    for (int i = 0; i < 8; ++i)
#pragma unroll
        for (int j = 0; j < 8; ++j) acc[i][j] = 0.f;

    float4 av = *(const float4*)(arp + aCol);
    float4 bv = *(const float4*)(Bg + (size_t)bRow * M_DIM + col0 + bCol);

#pragma unroll 1
    for (int k0 = 0; k0 < H_DIM; k0 += 8) {
        As[aCol + 0][aRow] = av.x;
        As[aCol + 1][aRow] = av.y;
        As[aCol + 2][aRow] = av.z;
        As[aCol + 3][aRow] = av.w;
        *(float4*)(&Bs[bRow][bCol]) = bv;
        __syncthreads();

        const int kn = k0 + 8;
        if (kn < H_DIM) {
            av = *(const float4*)(arp + kn + aCol);
            bv = *(const float4*)(Bg + (size_t)(kn + bRow) * M_DIM + col0 + bCol);
        }

#pragma unroll
        for (int k = 0; k < 8; ++k) {
            float ra[8], rb[8];
            *(float4*)&ra[0] = *(const float4*)&As[k][ty * 4];
            *(float4*)&ra[4] = *(const float4*)&As[k][ty * 4 + 64];
            *(float4*)&rb[0] = *(const float4*)&Bs[k][tx * 4];
            *(float4*)&rb[4] = *(const float4*)&Bs[k][tx * 4 + 64];
#pragma unroll
            for (int i = 0; i < 8; ++i)
#pragma unroll
                for (int j = 0; j < 8; ++j)
                    acc[i][j] = fmaf(ra[i], rb[j], acc[i][j]);
        }
        __syncthreads();
    }

    const float* b2e = b2 + e * M_DIM + col0;
    float bcol[8];
#pragma unroll
    for (int j = 0; j < 8; ++j) {
        const int c = (j < 4) ? (tx * 4 + j) : (64 + tx * 4 + (j - 4));
        bcol[j] = b2e[c];
    }
#pragma unroll
    for (int i = 0; i < 8; ++i) {
        const int rloc = (i < 4) ? (ty * 4 + i) : (64 + ty * 4 + (i - 4));
        const int t = stok[rloc];
        if (t < 0) continue;                        // empty slot -> token outputs stay 0
        const float g = sg[rloc];
        float* op = out + (size_t)t * M_DIM + col0;
        float4 v0, v1;
        v0.x = g * (acc[i][0] + bcol[0]);
        v0.y = g * (acc[i][1] + bcol[1]);
        v0.z = g * (acc[i][2] + bcol[2]);
        v0.w = g * (acc[i][3] + bcol[3]);
        v1.x = g * (acc[i][4] + bcol[4]);
        v1.y = g * (acc[i][5] + bcol[5]);
        v1.z = g * (acc[i][6] + bcol[6]);
        v1.w = g * (acc[i][7] + bcol[7]);
        *(float4*)(op + tx * 4)      = v0;
        *(float4*)(op + 64 + tx * 4) = v1;
    }
}

// ---------------------------------------------------------------------------
// launch
// ---------------------------------------------------------------------------
extern "C" void kernel_launch(void* const* d_in, const int* in_sizes, int n_in,
                              void* d_out, int out_size)
{
    const float* x  = (const float*)d_in[0];
    const float* wg = (const float*)d_in[1];
    const float* w1 = (const float*)d_in[2];
    const float* b1 = (const float*)d_in[3];
    const float* w2 = (const float*)d_in[4];
    const float* b2 = (const float*)d_in[5];
    float* out = (float*)d_out;

    init_kernel<<<256, 256>>>(out);
    gate_kernel<<<N_TOK, 256>>>(x, wg);
    sched_kernel<<<1, 256>>>(out, (out_size > N_TOK * M_DIM) ? 1 : 0);

    dim3 g1(H_DIM / 128, EC_SLOTS / 128);   // (64, 64)
    gemm1_kernel<<<g1, 256>>>(x, w1, b1);

    dim3 g2(M_DIM / 128, EC_SLOTS / 128);   // (16, 64)
    gemm2_kernel<<<g2, 256>>>(w2, b2, out);
}

// round 5
// speedup vs baseline: 1.1001x; 1.1001x over previous
#include <cuda_runtime.h>
#include <cstdint>

// ---------------------------------------------------------------------------
// Problem constants (fixed shapes from reference_code)
// ---------------------------------------------------------------------------
#define N_TOK   8192          // S*T tokens
#define M_DIM   2048          // model dim
#define E_NUM   8             // experts
#define H_DIM   8192          // FFN hidden
#define C_CAP   1024          // capacity per expert
#define EC_SLOTS 8192         // E * C

// ---------------------------------------------------------------------------
// Scratch (device globals; no dynamic allocation allowed)
// ---------------------------------------------------------------------------
__device__ int   g_idx  [N_TOK];                 // argmax expert per token
__device__ float g_gate1[N_TOK];                 // top-1 gate value per token
__device__ float g_gates[N_TOK * E_NUM];         // full softmax (for l_aux me)
__device__ int   g_s2t  [EC_SLOTS];              // slot -> token (-1 empty)
__device__ float g_h    [(size_t)EC_SLOTS * H_DIM];  // 256 MB FFN hidden

// ---------------------------------------------------------------------------
// packed fp32x2 helpers (Blackwell FFMA2 path — 2x fp32 FMA per instruction)
// ---------------------------------------------------------------------------
__device__ __forceinline__ unsigned long long f2_fma(unsigned long long a,
                                                     unsigned long long b,
                                                     unsigned long long c)
{
    unsigned long long d;
    asm("fma.rn.f32x2 %0, %1, %2, %3;" : "=l"(d) : "l"(a), "l"(b), "l"(c));
    return d;
}
__device__ __forceinline__ unsigned long long f2_dup(float v)
{
    unsigned long long d;
    asm("mov.b64 %0, {%1, %1};" : "=l"(d) : "f"(v));
    return d;
}
__device__ __forceinline__ float2 f2_unpack(unsigned long long v)
{
    float2 r;
    asm("mov.b64 {%0, %1}, %2;" : "=f"(r.x), "=f"(r.y) : "l"(v));
    return r;
}

// ---------------------------------------------------------------------------
// init: slot table to -1, zero the output tensor region
// ---------------------------------------------------------------------------
__global__ void init_kernel(float* __restrict__ out)
{
    int tid = blockIdx.x * blockDim.x + threadIdx.x;
    if (tid < EC_SLOTS) g_s2t[tid] = -1;
    float4* o4 = (float4*)out;
    const int n4 = (N_TOK * M_DIM) / 4;
    const int stride = gridDim.x * blockDim.x;
    for (int i = tid; i < n4; i += stride)
        o4[i] = make_float4(0.f, 0.f, 0.f, 0.f);
}

// ---------------------------------------------------------------------------
// gate: per-token logits (8 dots of length 2048), softmax, argmax
// one block per token; warp w computes expert w's logit
// ---------------------------------------------------------------------------
__global__ __launch_bounds__(256) void gate_kernel(
    const float* __restrict__ x,
    const float* __restrict__ wg)
{
    __shared__ float sx[M_DIM];
    __shared__ float slog[E_NUM];

    const int tok = blockIdx.x;
    const int tid = threadIdx.x;

    const float4* xr = (const float4*)(x + (size_t)tok * M_DIM);
    float4* sx4 = (float4*)sx;
    for (int i = tid; i < M_DIM / 4; i += 256) sx4[i] = xr[i];
    __syncthreads();

    const int wid = tid >> 5, lane = tid & 31;
    const float* __restrict__ w = wg + wid * M_DIM;
    float sum = 0.f;
    for (int m = lane; m < M_DIM; m += 32) sum = fmaf(sx[m], w[m], sum);
#pragma unroll
    for (int o = 16; o; o >>= 1) sum += __shfl_xor_sync(0xffffffffu, sum, o);
    if (lane == 0) slog[wid] = sum;
    __syncthreads();

    if (tid == 0) {
        float mx = slog[0]; int am = 0;
#pragma unroll
        for (int e = 1; e < E_NUM; ++e)
            if (slog[e] > mx) { mx = slog[e]; am = e; }   // first-max, matches jnp.argmax
        float ge[E_NUM], den = 0.f;
#pragma unroll
        for (int e = 0; e < E_NUM; ++e) { ge[e] = expf(slog[e] - mx); den += ge[e]; }
        const float inv = 1.f / den;
#pragma unroll
        for (int e = 0; e < E_NUM; ++e) g_gates[tok * E_NUM + e] = ge[e] * inv;
        g_idx[tok]   = am;
        g_gate1[tok] = ge[am] * inv;
    }
}

// ---------------------------------------------------------------------------
// sched: order-preserving capacity assignment (exact cumsum semantics),
// plus l_aux = sum(me*ce) * E / N^2 written to out[N*M] when requested.
// single block, warp e owns expert e.
// ---------------------------------------------------------------------------
__global__ __launch_bounds__(256) void sched_kernel(float* __restrict__ out,
                                                    int write_laux)
{
    __shared__ int   s_ce[E_NUM];
    __shared__ float s_me[E_NUM];

    const int tid = threadIdx.x;
    const int wid = tid >> 5, lane = tid & 31;

    int count = 0;
    for (int base = 0; base < N_TOK; base += 32) {
        const int tok = base + lane;
        const bool mine = (g_idx[tok] == wid);
        const unsigned bal = __ballot_sync(0xffffffffu, mine);
        if (mine) {
            const int loc = count + __popc(bal & ((1u << lane) - 1u));
            if (loc < C_CAP) g_s2t[wid * C_CAP + loc] = tok;
        }
        count += __popc(bal);
    }
    if (lane == 0) s_ce[wid] = count;

    float me = 0.f;
    for (int t = lane; t < N_TOK; t += 32) me += g_gates[t * E_NUM + wid];
#pragma unroll
    for (int o = 16; o; o >>= 1) me += __shfl_xor_sync(0xffffffffu, me, o);
    if (lane == 0) s_me[wid] = me;
    __syncthreads();

    if (tid == 0 && write_laux) {
        float acc = 0.f;
#pragma unroll
        for (int e = 0; e < E_NUM; ++e) acc += s_me[e] * (float)s_ce[e];
        out[(size_t)N_TOK * M_DIM] =
            acc * ((float)E_NUM / ((float)N_TOK * (float)N_TOK));
    }
}

// ---------------------------------------------------------------------------
// GEMM1: h[slot, :] = relu( x[token(slot), :] @ w1[e] + b1[e] )
// 128x128 tile, 8x8 per thread computed as 4 row-pairs x 8 cols via fma.f32x2.
// ---------------------------------------------------------------------------
__global__ __launch_bounds__(256) void gemm1_kernel(
    const float* __restrict__ x,
    const float* __restrict__ w1,
    const float* __restrict__ b1)
{
    __shared__ float As[8][128];
    __shared__ float Bs[8][128];
    __shared__ const float* srow[128];

    const int tid  = threadIdx.x;
    const int row0 = blockIdx.y * 128;
    const int col0 = blockIdx.x * 128;
    const int e    = row0 / C_CAP;                    // 128-row tile never crosses experts
    const float* __restrict__ Bg = w1 + (size_t)e * M_DIM * H_DIM;

    if (tid < 128) {
        const int t = g_s2t[row0 + tid];
        srow[tid] = (t >= 0) ? (x + (size_t)t * M_DIM) : (const float*)nullptr;
    }
    __syncthreads();

    const int aRow = tid >> 1;
    const int aCol = (tid & 1) << 2;
    const int bRow = tid >> 5;
    const int bCol = (tid & 31) << 2;
    const int tx = tid & 15;
    const int ty = tid >> 4;

    const float* arp = srow[aRow];

    unsigned long long acc2[4][8];
#pragma unroll
    for (int p = 0; p < 4; ++p)
#pragma unroll
        for (int j = 0; j < 8; ++j) acc2[p][j] = 0ULL;

    float4 av = arp ? *(const float4*)(arp + aCol)
                    : make_float4(0.f, 0.f, 0.f, 0.f);
    float4 bv = *(const float4*)(Bg + (size_t)bRow * H_DIM + col0 + bCol);

#pragma unroll 1
    for (int k0 = 0; k0 < M_DIM; k0 += 8) {
        As[aCol + 0][aRow] = av.x;
        As[aCol + 1][aRow] = av.y;
        As[aCol + 2][aRow] = av.z;
        As[aCol + 3][aRow] = av.w;
        *(float4*)(&Bs[bRow][bCol]) = bv;
        __syncthreads();

        const int kn = k0 + 8;
        if (kn < M_DIM) {
            av = arp ? *(const float4*)(arp + kn + aCol)
                     : make_float4(0.f, 0.f, 0.f, 0.f);
            bv = *(const float4*)(Bg + (size_t)(kn + bRow) * H_DIM + col0 + bCol);
        }

#pragma unroll
        for (int k = 0; k < 8; ++k) {
            // A row-pairs: packed directly from smem (rows are adjacent floats)
            ulonglong2 a01 = *(const ulonglong2*)(&As[k][ty * 4]);
            ulonglong2 a23 = *(const ulonglong2*)(&As[k][ty * 4 + 64]);
            unsigned long long a2[4] = { a01.x, a01.y, a23.x, a23.y };
            // B cols: duplicate each scalar into both lanes
            float4 rb0 = *(const float4*)(&Bs[k][tx * 4]);
            float4 rb1 = *(const float4*)(&Bs[k][tx * 4 + 64]);
            unsigned long long b2[8];
            b2[0] = f2_dup(rb0.x); b2[1] = f2_dup(rb0.y);
            b2[2] = f2_dup(rb0.z); b2[3] = f2_dup(rb0.w);
            b2[4] = f2_dup(rb1.x); b2[5] = f2_dup(rb1.y);
            b2[6] = f2_dup(rb1.z); b2[7] = f2_dup(rb1.w);
#pragma unroll
            for (int p = 0; p < 4; ++p)
#pragma unroll
                for (int j = 0; j < 8; ++j)
                    acc2[p][j] = f2_fma(a2[p], b2[j], acc2[p][j]);
        }
        __syncthreads();
    }

    // epilogue: relu(acc + b1), write pairs of rows
    const float* b1e = b1 + e * H_DIM + col0;
    float bcol[8];
#pragma unroll
    for (int j = 0; j < 8; ++j)
        bcol[j] = b1e[(j < 4) ? (tx * 4 + j) : (64 + tx * 4 + (j - 4))];

#pragma unroll
    for (int p = 0; p < 4; ++p) {
        const int rA = row0 + ((p < 2) ? (ty * 4 + 2 * p)
                                       : (64 + ty * 4 + 2 * (p - 2)));
        float vlo[8], vhi[8];
#pragma unroll
        for (int j = 0; j < 8; ++j) {
            float2 t = f2_unpack(acc2[p][j]);
            vlo[j] = fmaxf(t.x + bcol[j], 0.f);
            vhi[j] = fmaxf(t.y + bcol[j], 0.f);
        }
        float* hpA = g_h + (size_t)rA * H_DIM + col0;
        float* hpB = hpA + H_DIM;             // rB = rA + 1
        *(float4*)(hpA + tx * 4)      = make_float4(vlo[0], vlo[1], vlo[2], vlo[3]);
        *(float4*)(hpA + 64 + tx * 4) = make_float4(vlo[4], vlo[5], vlo[6], vlo[7]);
        *(float4*)(hpB + tx * 4)      = make_float4(vhi[0], vhi[1], vhi[2], vhi[3]);
        *(float4*)(hpB + 64 + tx * 4) = make_float4(vhi[4], vhi[5], vhi[6], vhi[7]);
    }
}

// ---------------------------------------------------------------------------
// GEMM2: out[token(slot), :] = gate1(token) * ( h[slot, :] @ w2[e] + b2[e] )
// ---------------------------------------------------------------------------
__global__ __launch_bounds__(256) void gemm2_kernel(
    const float* __restrict__ w2,
    const float* __restrict__ b2,
    float* __restrict__ out)
{
    __shared__ float As[8][128];
    __shared__ float Bs[8][128];
    __shared__ int   stok[128];
    __shared__ float sg[128];

    const int tid  = threadIdx.x;
    const int row0 = blockIdx.y * 128;
    const int col0 = blockIdx.x * 128;
    const int e    = row0 / C_CAP;
    const float* __restrict__ Bg = w2 + (size_t)e * H_DIM * M_DIM;

    if (tid < 128) {
        const int t = g_s2t[row0 + tid];
        stok[tid] = t;
        sg[tid]   = (t >= 0) ? g_gate1[t] : 0.f;
    }
    __syncthreads();

    const int aRow = tid >> 1;
    const int aCol = (tid & 1) << 2;
    const int bRow = tid >> 5;
    const int bCol = (tid & 31) << 2;
    const int tx = tid & 15;
    const int ty = tid >> 4;

    const float* arp = g_h + (size_t)(row0 + aRow) * H_DIM;

    unsigned long long acc2[4][8];
#pragma unroll
    for (int p = 0; p < 4; ++p)
#pragma unroll
        for (int j = 0; j < 8; ++j) acc2[p][j] = 0ULL;

    float4 av = *(const float4*)(arp + aCol);
    float4 bv = *(const float4*)(Bg + (size_t)bRow * M_DIM + col0 + bCol);

#pragma unroll 1
    for (int k0 = 0; k0 < H_DIM; k0 += 8) {
        As[aCol + 0][aRow] = av.x;
        As[aCol + 1][aRow] = av.y;
        As[aCol + 2][aRow] = av.z;
        As[aCol + 3][aRow] = av.w;
        *(float4*)(&Bs[bRow][bCol]) = bv;
        __syncthreads();

        const int kn = k0 + 8;
        if (kn < H_DIM) {
            av = *(const float4*)(arp + kn + aCol);
            bv = *(const float4*)(Bg + (size_t)(kn + bRow) * M_DIM + col0 + bCol);
        }

#pragma unroll
        for (int k = 0; k < 8; ++k) {
            ulonglong2 a01 = *(const ulonglong2*)(&As[k][ty * 4]);
            ulonglong2 a23 = *(const ulonglong2*)(&As[k][ty * 4 + 64]);
            unsigned long long a2[4] = { a01.x, a01.y, a23.x, a23.y };
            float4 rb0 = *(const float4*)(&Bs[k][tx * 4]);
            float4 rb1 = *(const float4*)(&Bs[k][tx * 4 + 64]);
            unsigned long long b2p[8];
            b2p[0] = f2_dup(rb0.x); b2p[1] = f2_dup(rb0.y);
            b2p[2] = f2_dup(rb0.z); b2p[3] = f2_dup(rb0.w);
            b2p[4] = f2_dup(rb1.x); b2p[5] = f2_dup(rb1.y);
            b2p[6] = f2_dup(rb1.z); b2p[7] = f2_dup(rb1.w);
#pragma unroll
            for (int p = 0; p < 4; ++p)
#pragma unroll
                for (int j = 0; j < 8; ++j)
                    acc2[p][j] = f2_fma(a2[p], b2p[j], acc2[p][j]);
        }
        __syncthreads();
    }

    const float* b2e = b2 + e * M_DIM + col0;
    float bcol[8];
#pragma unroll
    for (int j = 0; j < 8; ++j)
        bcol[j] = b2e[(j < 4) ? (tx * 4 + j) : (64 + tx * 4 + (j - 4))];

#pragma unroll
    for (int p = 0; p < 4; ++p) {
        const int rlocA = (p < 2) ? (ty * 4 + 2 * p) : (64 + ty * 4 + 2 * (p - 2));
        float vlo[8], vhi[8];
#pragma unroll
        for (int j = 0; j < 8; ++j) {
            float2 t = f2_unpack(acc2[p][j]);
            vlo[j] = t.x + bcol[j];
            vhi[j] = t.y + bcol[j];
        }
        // row A
        {
            const int t = stok[rlocA];
            if (t >= 0) {
                const float g = sg[rlocA];
                float* op = out + (size_t)t * M_DIM + col0;
                *(float4*)(op + tx * 4) =
                    make_float4(g * vlo[0], g * vlo[1], g * vlo[2], g * vlo[3]);
                *(float4*)(op + 64 + tx * 4) =
                    make_float4(g * vlo[4], g * vlo[5], g * vlo[6], g * vlo[7]);
            }
        }
        // row B = row A + 1
        {
            const int t = stok[rlocA + 1];
            if (t >= 0) {
                const float g = sg[rlocA + 1];
                float* op = out + (size_t)t * M_DIM + col0;
                *(float4*)(op + tx * 4) =
                    make_float4(g * vhi[0], g * vhi[1], g * vhi[2], g * vhi[3]);
                *(float4*)(op + 64 + tx * 4) =
                    make_float4(g * vhi[4], g * vhi[5], g * vhi[6], g * vhi[7]);
            }
        }
    }
}

// ---------------------------------------------------------------------------
// launch
// ---------------------------------------------------------------------------
extern "C" void kernel_launch(void* const* d_in, const int* in_sizes, int n_in,
                              void* d_out, int out_size)
{
    const float* x  = (const float*)d_in[0];
    const float* wg = (const float*)d_in[1];
    const float* w1 = (const float*)d_in[2];
    const float* b1 = (const float*)d_in[3];
    const float* w2 = (const float*)d_in[4];
    const float* b2 = (const float*)d_in[5];
    float* out = (float*)d_out;

    init_kernel<<<256, 256>>>(out);
    gate_kernel<<<N_TOK, 256>>>(x, wg);
    sched_kernel<<<1, 256>>>(out, (out_size > N_TOK * M_DIM) ? 1 : 0);

    dim3 g1(H_DIM / 128, EC_SLOTS / 128);   // (64, 64)
    gemm1_kernel<<<g1, 256>>>(x, w1, b1);

    dim3 g2(M_DIM / 128, EC_SLOTS / 128);   // (16, 64)
    gemm2_kernel<<<g2, 256>>>(w2, b2, out);
}

// round 7
// speedup vs baseline: 1.8802x; 1.7092x over previous
#include <cuda_runtime.h>
#include <cuda_bf16.h>
#include <cstdint>

// ---------------------------------------------------------------------------
// Problem constants
// ---------------------------------------------------------------------------
#define N_TOK    8192
#define M_DIM    2048
#define E_NUM    8
#define H_DIM    8192
#define C_CAP    1024
#define EC_SLOTS 8192

// GEMM tiling: block 128x128, 8 warps (2m x 4n), warp tile 64x32, K-chunk 32
#define KCHUNK   32
#define ROW_STRIDE_EL 40            // padded smem row: 32 bf16 + 8 pad (80 B)
#define ROW_STRIDE_B  80
#define SPLIT_B  (128 * ROW_STRIDE_B)        // 10240 per split
#define STAGE_B  (4 * SPLIT_B)               // Ah, Al, Bh, Bl = 40960
#define NSTAGE   5
#define SMEM_BYTES (NSTAGE * STAGE_B)        // 204800

// ---------------------------------------------------------------------------
// Scratch (device globals; no dynamic allocation allowed)
// ---------------------------------------------------------------------------
__device__ int   g_idx  [N_TOK];
__device__ float g_gate1[N_TOK];
__device__ float g_gates[N_TOK * E_NUM];
__device__ int   g_s2t  [EC_SLOTS];

__device__ __nv_bfloat16 g_disp_hi[(size_t)EC_SLOTS * M_DIM];
__device__ __nv_bfloat16 g_disp_lo[(size_t)EC_SLOTS * M_DIM];
__device__ __nv_bfloat16 g_h_hi   [(size_t)EC_SLOTS * H_DIM];
__device__ __nv_bfloat16 g_h_lo   [(size_t)EC_SLOTS * H_DIM];
// transposed bf16 weight splits: w1T [E][H][M], w2T [E][M][H]  (K contiguous)
__device__ __nv_bfloat16 g_w1t_hi[(size_t)E_NUM * H_DIM * M_DIM];
__device__ __nv_bfloat16 g_w1t_lo[(size_t)E_NUM * H_DIM * M_DIM];
__device__ __nv_bfloat16 g_w2t_hi[(size_t)E_NUM * M_DIM * H_DIM];
__device__ __nv_bfloat16 g_w2t_lo[(size_t)E_NUM * M_DIM * H_DIM];

// ---------------------------------------------------------------------------
// helpers
// ---------------------------------------------------------------------------
__device__ __forceinline__ uint32_t s2u(const void* p) {
    return (uint32_t)__cvta_generic_to_shared(p);
}
__device__ __forceinline__ void cp16(uint32_t s, const void* g) {
    asm volatile("cp.async.cg.shared.global [%0], [%1], 16;" :: "r"(s), "l"(g));
}
__device__ __forceinline__ void ldsm4(uint32_t* r, uint32_t a) {
    asm volatile("ldmatrix.sync.aligned.m8n8.x4.shared.b16 {%0,%1,%2,%3}, [%4];"
                 : "=r"(r[0]), "=r"(r[1]), "=r"(r[2]), "=r"(r[3]) : "r"(a));
}
__device__ __forceinline__ void ldsm2(uint32_t* r, uint32_t a) {
    asm volatile("ldmatrix.sync.aligned.m8n8.x2.shared.b16 {%0,%1}, [%2];"
                 : "=r"(r[0]), "=r"(r[1]) : "r"(a));
}
__device__ __forceinline__ void mmabf16(float* d, const uint32_t* a, const uint32_t* b) {
    asm volatile("mma.sync.aligned.m16n8k16.row.col.f32.bf16.bf16.f32 "
                 "{%0,%1,%2,%3}, {%4,%5,%6,%7}, {%8,%9}, {%0,%1,%2,%3};"
                 : "+f"(d[0]), "+f"(d[1]), "+f"(d[2]), "+f"(d[3])
                 : "r"(a[0]), "r"(a[1]), "r"(a[2]), "r"(a[3]),
                   "r"(b[0]), "r"(b[1]));
}
__device__ __forceinline__ void bsplit(float f, __nv_bfloat16& hi, __nv_bfloat16& lo)
{
    hi = __float2bfloat16(f);
    lo = __float2bfloat16(f - __bfloat162float(hi));
}

// ---------------------------------------------------------------------------
// init: slot table to -1, zero output
// ---------------------------------------------------------------------------
__global__ void init_kernel(float* __restrict__ out)
{
    int tid = blockIdx.x * blockDim.x + threadIdx.x;
    if (tid < EC_SLOTS) g_s2t[tid] = -1;
    float4* o4 = (float4*)out;
    const int n4 = (N_TOK * M_DIM) / 4;
    const int stride = gridDim.x * blockDim.x;
    for (int i = tid; i < n4; i += stride)
        o4[i] = make_float4(0.f, 0.f, 0.f, 0.f);
}

// ---------------------------------------------------------------------------
// gate: exact fp32 routing (proven exact vs reference)
// ---------------------------------------------------------------------------
__global__ __launch_bounds__(256) void gate_kernel(
    const float* __restrict__ x, const float* __restrict__ wg)
{
    __shared__ float sx[M_DIM];
    __shared__ float slog[E_NUM];

    const int tok = blockIdx.x;
    const int tid = threadIdx.x;

    const float4* xr = (const float4*)(x + (size_t)tok * M_DIM);
    float4* sx4 = (float4*)sx;
    for (int i = tid; i < M_DIM / 4; i += 256) sx4[i] = xr[i];
    __syncthreads();

    const int wid = tid >> 5, lane = tid & 31;
    const float* __restrict__ w = wg + wid * M_DIM;
    float sum = 0.f;
    for (int m = lane; m < M_DIM; m += 32) sum = fmaf(sx[m], w[m], sum);
#pragma unroll
    for (int o = 16; o; o >>= 1) sum += __shfl_xor_sync(0xffffffffu, sum, o);
    if (lane == 0) slog[wid] = sum;
    __syncthreads();

    if (tid == 0) {
        float mx = slog[0]; int am = 0;
#pragma unroll
        for (int e = 1; e < E_NUM; ++e)
            if (slog[e] > mx) { mx = slog[e]; am = e; }
        float ge[E_NUM], den = 0.f;
#pragma unroll
        for (int e = 0; e < E_NUM; ++e) { ge[e] = expf(slog[e] - mx); den += ge[e]; }
        const float inv = 1.f / den;
#pragma unroll
        for (int e = 0; e < E_NUM; ++e) g_gates[tok * E_NUM + e] = ge[e] * inv;
        g_idx[tok]   = am;
        g_gate1[tok] = ge[am] * inv;
    }
}

// ---------------------------------------------------------------------------
// sched: exact cumsum capacity assignment + l_aux
// ---------------------------------------------------------------------------
__global__ __launch_bounds__(256) void sched_kernel(float* __restrict__ out,
                                                    int write_laux)
{
    __shared__ int   s_ce[E_NUM];
    __shared__ float s_me[E_NUM];

    const int tid = threadIdx.x;
    const int wid = tid >> 5, lane = tid & 31;

    int count = 0;
    for (int base = 0; base < N_TOK; base += 32) {
        const int tok = base + lane;
        const bool mine = (g_idx[tok] == wid);
        const unsigned bal = __ballot_sync(0xffffffffu, mine);
        if (mine) {
            const int loc = count + __popc(bal & ((1u << lane) - 1u));
            if (loc < C_CAP) g_s2t[wid * C_CAP + loc] = tok;
        }
        count += __popc(bal);
    }
    if (lane == 0) s_ce[wid] = count;

    float me = 0.f;
    for (int t = lane; t < N_TOK; t += 32) me += g_gates[t * E_NUM + wid];
#pragma unroll
    for (int o = 16; o; o >>= 1) me += __shfl_xor_sync(0xffffffffu, me, o);
    if (lane == 0) s_me[wid] = me;
    __syncthreads();

    if (tid == 0 && write_laux) {
        float acc = 0.f;
#pragma unroll
        for (int e = 0; e < E_NUM; ++e) acc += s_me[e] * (float)s_ce[e];
        out[(size_t)N_TOK * M_DIM] =
            acc * ((float)E_NUM / ((float)N_TOK * (float)N_TOK));
    }
}

// ---------------------------------------------------------------------------
// disp: gather token rows into slot order, split fp32 -> bf16 hi/lo
// ---------------------------------------------------------------------------
__global__ __launch_bounds__(256) void disp_kernel(const float* __restrict__ x)
{
    const int slot = blockIdx.x;
    const int t = g_s2t[slot];
    const float4* src = (t >= 0) ? (const float4*)(x + (size_t)t * M_DIM) : nullptr;
    __nv_bfloat16* dh = g_disp_hi + (size_t)slot * M_DIM;
    __nv_bfloat16* dl = g_disp_lo + (size_t)slot * M_DIM;
    for (int i = threadIdx.x; i < M_DIM / 4; i += 256) {
        float4 v = src ? src[i] : make_float4(0.f, 0.f, 0.f, 0.f);
        __nv_bfloat16 hh[4], ll[4];
        bsplit(v.x, hh[0], ll[0]); bsplit(v.y, hh[1], ll[1]);
        bsplit(v.z, hh[2], ll[2]); bsplit(v.w, hh[3], ll[3]);
        *(uint2*)(dh + i * 4) = *(uint2*)hh;
        *(uint2*)(dl + i * 4) = *(uint2*)ll;
    }
}

// ---------------------------------------------------------------------------
// weight transpose + split: src [E][R][C] fp32 -> dst [E][C][R] bf16 hi/lo
// ---------------------------------------------------------------------------
__global__ void wsplit_kernel(const float* __restrict__ src,
                              __nv_bfloat16* __restrict__ dhi,
                              __nv_bfloat16* __restrict__ dlo,
                              int R, int C)
{
    __shared__ float tile[32][33];
    const int e  = blockIdx.z;
    const int c0 = blockIdx.x * 32;
    const int r0 = blockIdx.y * 32;
    const int tx = threadIdx.x, ty = threadIdx.y;

    const float* s = src + (size_t)e * R * C;
#pragma unroll
    for (int i = 0; i < 4; ++i)
        tile[ty + 8 * i][tx] = s[(size_t)(r0 + ty + 8 * i) * C + c0 + tx];
    __syncthreads();

    __nv_bfloat16* dh = dhi + (size_t)e * C * R;
    __nv_bfloat16* dl = dlo + (size_t)e * C * R;
#pragma unroll
    for (int i = 0; i < 4; ++i) {
        const int c = c0 + ty + 8 * i;
        const int r = r0 + tx;
        __nv_bfloat16 hi, lo;
        bsplit(tile[tx][ty + 8 * i], hi, lo);
        dh[(size_t)c * R + r] = hi;
        dl[(size_t)c * R + r] = lo;
    }
}

// ---------------------------------------------------------------------------
// HMMA mainloop: acc += A @ B^T with 3-term bf16 split, 5-stage cp.async pipe
//   A: [128 rows @ row0][K] hi/lo, K-major, pitch bytes = K*2
//   B: [128 rows @ col0][K] hi/lo, K-major
//   acc[mi][ni][4] per thread, warp grid 2m x 4n, warp tile 64x32
// ---------------------------------------------------------------------------
__device__ __forceinline__ void hmma_mainloop(
    const char* __restrict__ Ah, const char* __restrict__ Al,
    const char* __restrict__ Bh, const char* __restrict__ Bl,
    size_t pitch, int chunks, char* smem, float acc[4][4][4])
{
    const int tid  = threadIdx.x;
    const int wid  = tid >> 5, lane = tid & 31;
    const int wm   = (wid & 1) * 64;
    const int wn   = (wid >> 1) * 32;
    const uint32_t sbase = s2u(smem);

    // stage loader: 512 16B units per split, 8 cp16 per thread per stage
    auto load_stage = [&](int st, int c) {
        const uint32_t sb = sbase + st * STAGE_B;
        const size_t kb = (size_t)c * (KCHUNK * 2);
#pragma unroll
        for (int i = 0; i < 2; ++i) {
            const int u = tid + i * 256;
            const int row = u >> 2, g = u & 3;
            const uint32_t so = row * ROW_STRIDE_B + g * 16;
            const size_t go = (size_t)row * pitch + kb + g * 16;
            cp16(sb + 0 * SPLIT_B + so, Ah + go);
            cp16(sb + 1 * SPLIT_B + so, Al + go);
            cp16(sb + 2 * SPLIT_B + so, Bh + go);
            cp16(sb + 3 * SPLIT_B + so, Bl + go);
        }
        asm volatile("cp.async.commit_group;");
    };

    // prologue: prefetch NSTAGE-1 stages
#pragma unroll
    for (int s = 0; s < NSTAGE - 1; ++s) load_stage(s, s);

    int buf = 0;
#pragma unroll 1
    for (int c = 0; c < chunks; ++c) {
        asm volatile("cp.async.wait_group %0;" :: "n"(NSTAGE - 2) : "memory");
        __syncthreads();

        if (c + NSTAGE - 1 < chunks)
            load_stage((c + NSTAGE - 1) % NSTAGE, c + NSTAGE - 1);

        const uint32_t sb = sbase + buf * STAGE_B;
#pragma unroll
        for (int ks = 0; ks < 2; ++ks) {
            const int kb2 = ks * 32;   // 16 elements * 2 bytes
            uint32_t ah[4][4], al[4][4], bh[4][2], bl[4][2];

            const uint32_t aoff = (uint32_t)((wm + (lane & 15)) * ROW_STRIDE_B
                                             + kb2 + ((lane >> 4) & 1) * 16);
#pragma unroll
            for (int mi = 0; mi < 4; ++mi) {
                const uint32_t ad = sb + aoff + mi * 16 * ROW_STRIDE_B;
                ldsm4(ah[mi], ad);
                ldsm4(al[mi], ad + SPLIT_B);
            }
            const uint32_t boff = (uint32_t)((wn + (lane & 7)) * ROW_STRIDE_B
                                             + kb2 + ((lane >> 3) & 1) * 16);
#pragma unroll
            for (int ni = 0; ni < 4; ++ni) {
                const uint32_t bd = sb + 2 * SPLIT_B + boff + ni * 8 * ROW_STRIDE_B;
                ldsm2(bh[ni], bd);
                ldsm2(bl[ni], bd + SPLIT_B);
            }
#pragma unroll
            for (int mi = 0; mi < 4; ++mi)
#pragma unroll
                for (int ni = 0; ni < 4; ++ni) {
                    mmabf16(acc[mi][ni], ah[mi], bh[ni]);
                    mmabf16(acc[mi][ni], al[mi], bh[ni]);
                    mmabf16(acc[mi][ni], ah[mi], bl[ni]);
                }
        }
        buf = (buf + 1 == NSTAGE) ? 0 : buf + 1;
        __syncthreads();
    }
}

// ---------------------------------------------------------------------------
// GEMM1: h[slot] = relu( disp[slot] @ w1[e]^T(cols) + b1[e] ) -> split hi/lo
// ---------------------------------------------------------------------------
__global__ __launch_bounds__(256, 1) void gemm1_mma(const float* __restrict__ b1)
{
    extern __shared__ char smem[];
    const int tid = threadIdx.x;
    const int wid = tid >> 5, lane = tid & 31;
    const int row0 = blockIdx.y * 128;
    const int col0 = blockIdx.x * 128;
    const int e    = row0 >> 10;

    float acc[4][4][4];
#pragma unroll
    for (int mi = 0; mi < 4; ++mi)
#pragma unroll
        for (int ni = 0; ni < 4; ++ni)
#pragma unroll
            for (int k = 0; k < 4; ++k) acc[mi][ni][k] = 0.f;

    hmma_mainloop(
        (const char*)(g_disp_hi + (size_t)row0 * M_DIM),
        (const char*)(g_disp_lo + (size_t)row0 * M_DIM),
        (const char*)(g_w1t_hi + (size_t)e * H_DIM * M_DIM + (size_t)col0 * M_DIM),
        (const char*)(g_w1t_lo + (size_t)e * H_DIM * M_DIM + (size_t)col0 * M_DIM),
        (size_t)M_DIM * 2, M_DIM / KCHUNK, smem, acc);

    const int wm = (wid & 1) * 64;
    const int wn = (wid >> 1) * 32;
    const float* b1g = b1 + (size_t)e * H_DIM;

#pragma unroll
    for (int ni = 0; ni < 4; ++ni) {
        const int cg = col0 + wn + ni * 8 + (lane & 3) * 2;
        const float bv0 = b1g[cg], bv1 = b1g[cg + 1];
#pragma unroll
        for (int mi = 0; mi < 4; ++mi)
#pragma unroll
            for (int h = 0; h < 2; ++h) {
                const int rg = row0 + wm + mi * 16 + (lane >> 2) + h * 8;
                float v0 = fmaxf(acc[mi][ni][h * 2 + 0] + bv0, 0.f);
                float v1 = fmaxf(acc[mi][ni][h * 2 + 1] + bv1, 0.f);
                __nv_bfloat16 h0, l0, h1, l1;
                bsplit(v0, h0, l0);
                bsplit(v1, h1, l1);
                *(__nv_bfloat162*)(g_h_hi + (size_t)rg * H_DIM + cg) =
                    __nv_bfloat162(h0, h1);
                *(__nv_bfloat162*)(g_h_lo + (size_t)rg * H_DIM + cg) =
                    __nv_bfloat162(l0, l1);
            }
    }
}

// ---------------------------------------------------------------------------
// GEMM2: out[token(slot)] = gate1 * ( h[slot] @ w2[e]^T(cols) + b2[e] )
// ---------------------------------------------------------------------------
__global__ __launch_bounds__(256, 1) void gemm2_mma(const float* __restrict__ b2,
                                                    float* __restrict__ out)
{
    extern __shared__ char smem[];
    const int tid = threadIdx.x;
    const int wid = tid >> 5, lane = tid & 31;
    const int row0 = blockIdx.y * 128;
    const int col0 = blockIdx.x * 128;
    const int e    = row0 >> 10;

    float acc[4][4][4];
#pragma unroll
    for (int mi = 0; mi < 4; ++mi)
#pragma unroll
        for (int ni = 0; ni < 4; ++ni)
#pragma unroll
            for (int k = 0; k < 4; ++k) acc[mi][ni][k] = 0.f;

    hmma_mainloop(
        (const char*)(g_h_hi + (size_t)row0 * H_DIM),
        (const char*)(g_h_lo + (size_t)row0 * H_DIM),
        (const char*)(g_w2t_hi + (size_t)e * M_DIM * H_DIM + (size_t)col0 * H_DIM),
        (const char*)(g_w2t_lo + (size_t)e * M_DIM * H_DIM + (size_t)col0 * H_DIM),
        (size_t)H_DIM * 2, H_DIM / KCHUNK, smem, acc);

    const int wm = (wid & 1) * 64;
    const int wn = (wid >> 1) * 32;
    const float* b2g = b2 + (size_t)e * M_DIM;

#pragma unroll
    for (int ni = 0; ni < 4; ++ni) {
        const int cg = col0 + wn + ni * 8 + (lane & 3) * 2;
        const float bv0 = b2g[cg], bv1 = b2g[cg + 1];
#pragma unroll
        for (int mi = 0; mi < 4; ++mi)
#pragma unroll
            for (int h = 0; h < 2; ++h) {
                const int rg = row0 + wm + mi * 16 + (lane >> 2) + h * 8;
                const int t = g_s2t[rg];
                if (t < 0) continue;
                const float g = g_gate1[t];
                float2 v;
                v.x = (acc[mi][ni][h * 2 + 0] + bv0) * g;
                v.y = (acc[mi][ni][h * 2 + 1] + bv1) * g;
                *(float2*)(out + (size_t)t * M_DIM + cg) = v;
            }
    }
}

// ---------------------------------------------------------------------------
// launch
// ---------------------------------------------------------------------------
extern "C" void kernel_launch(void* const* d_in, const int* in_sizes, int n_in,
                              void* d_out, int out_size)
{
    const float* x  = (const float*)d_in[0];
    const float* wg = (const float*)d_in[1];
    const float* w1 = (const float*)d_in[2];
    const float* b1 = (const float*)d_in[3];
    const float* w2 = (const float*)d_in[4];
    const float* b2 = (const float*)d_in[5];
    float* out = (float*)d_out;

    cudaFuncSetAttribute(gemm1_mma, cudaFuncAttributeMaxDynamicSharedMemorySize,
                         SMEM_BYTES);
    cudaFuncSetAttribute(gemm2_mma, cudaFuncAttributeMaxDynamicSharedMemorySize,
                         SMEM_BYTES);

    __nv_bfloat16 *w1t_hi, *w1t_lo, *w2t_hi, *w2t_lo;
    cudaGetSymbolAddress((void**)&w1t_hi, g_w1t_hi);
    cudaGetSymbolAddress((void**)&w1t_lo, g_w1t_lo);
    cudaGetSymbolAddress((void**)&w2t_hi, g_w2t_hi);
    cudaGetSymbolAddress((void**)&w2t_lo, g_w2t_lo);

    init_kernel<<<256, 256>>>(out);

    wsplit_kernel<<<dim3(H_DIM / 32, M_DIM / 32, E_NUM), dim3(32, 8)>>>(
        w1, w1t_hi, w1t_lo, M_DIM, H_DIM);
    wsplit_kernel<<<dim3(M_DIM / 32, H_DIM / 32, E_NUM), dim3(32, 8)>>>(
        w2, w2t_hi, w2t_lo, H_DIM, M_DIM);

    gate_kernel<<<N_TOK, 256>>>(x, wg);
    sched_kernel<<<1, 256>>>(out, (out_size > N_TOK * M_DIM) ? 1 : 0);
    disp_kernel<<<EC_SLOTS, 256>>>(x);

    gemm1_mma<<<dim3(H_DIM / 128, EC_SLOTS / 128), 256, SMEM_BYTES>>>(b1);
    gemm2_mma<<<dim3(M_DIM / 128, EC_SLOTS / 128), 256, SMEM_BYTES>>>(b2, out);
}

// round 8
// speedup vs baseline: 1.9327x; 1.0279x over previous
#include <cuda_runtime.h>
#include <cuda_bf16.h>
#include <cstdint>

// ---------------------------------------------------------------------------
// Problem constants
// ---------------------------------------------------------------------------
#define N_TOK    8192
#define M_DIM    2048
#define E_NUM    8
#define H_DIM    8192
#define C_CAP    1024
#define EC_SLOTS 8192

// GEMM tiling: block 128x128, 16 warps (4m x 4n), warp tile 32x32, K-chunk 32
#define KCHUNK   32
#define ROW_STRIDE_B  80                     // 32 bf16 (64B) + 16B pad
#define SPLIT_B  (128 * ROW_STRIDE_B)        // 10240 per split
#define STAGE_B  (4 * SPLIT_B)               // Ah, Al, Bh, Bl = 40960
#define NSTAGE   5
#define SMEM_BYTES (NSTAGE * STAGE_B)        // 204800
#define NTHREADS 512

// ---------------------------------------------------------------------------
// Scratch (device globals; no dynamic allocation allowed)
// ---------------------------------------------------------------------------
__device__ int   g_idx  [N_TOK];
__device__ float g_gate1[N_TOK];
__device__ float g_gates[N_TOK * E_NUM];
__device__ int   g_s2t  [EC_SLOTS];

__device__ __nv_bfloat16 g_disp_hi[(size_t)EC_SLOTS * M_DIM];
__device__ __nv_bfloat16 g_disp_lo[(size_t)EC_SLOTS * M_DIM];
__device__ __nv_bfloat16 g_h_hi   [(size_t)EC_SLOTS * H_DIM];
__device__ __nv_bfloat16 g_h_lo   [(size_t)EC_SLOTS * H_DIM];
// transposed bf16 weight splits: w1T [E][H][M], w2T [E][M][H]  (K contiguous)
__device__ __nv_bfloat16 g_w1t_hi[(size_t)E_NUM * H_DIM * M_DIM];
__device__ __nv_bfloat16 g_w1t_lo[(size_t)E_NUM * H_DIM * M_DIM];
__device__ __nv_bfloat16 g_w2t_hi[(size_t)E_NUM * M_DIM * H_DIM];
__device__ __nv_bfloat16 g_w2t_lo[(size_t)E_NUM * M_DIM * H_DIM];

// ---------------------------------------------------------------------------
// helpers
// ---------------------------------------------------------------------------
__device__ __forceinline__ uint32_t s2u(const void* p) {
    return (uint32_t)__cvta_generic_to_shared(p);
}
__device__ __forceinline__ void cp16(uint32_t s, const void* g) {
    asm volatile("cp.async.cg.shared.global [%0], [%1], 16;" :: "r"(s), "l"(g));
}
__device__ __forceinline__ void ldsm4(uint32_t* r, uint32_t a) {
    asm volatile("ldmatrix.sync.aligned.m8n8.x4.shared.b16 {%0,%1,%2,%3}, [%4];"
                 : "=r"(r[0]), "=r"(r[1]), "=r"(r[2]), "=r"(r[3]) : "r"(a));
}
__device__ __forceinline__ void ldsm2(uint32_t* r, uint32_t a) {
    asm volatile("ldmatrix.sync.aligned.m8n8.x2.shared.b16 {%0,%1}, [%2];"
                 : "=r"(r[0]), "=r"(r[1]) : "r"(a));
}
__device__ __forceinline__ void mmabf16(float* d, const uint32_t* a, const uint32_t* b) {
    asm volatile("mma.sync.aligned.m16n8k16.row.col.f32.bf16.bf16.f32 "
                 "{%0,%1,%2,%3}, {%4,%5,%6,%7}, {%8,%9}, {%0,%1,%2,%3};"
                 : "+f"(d[0]), "+f"(d[1]), "+f"(d[2]), "+f"(d[3])
                 : "r"(a[0]), "r"(a[1]), "r"(a[2]), "r"(a[3]),
                   "r"(b[0]), "r"(b[1]));
}
__device__ __forceinline__ void bsplit(float f, __nv_bfloat16& hi, __nv_bfloat16& lo)
{
    hi = __float2bfloat16(f);
    lo = __float2bfloat16(f - __bfloat162float(hi));
}

// ---------------------------------------------------------------------------
// init: slot table to -1, zero output
// ---------------------------------------------------------------------------
__global__ void init_kernel(float* __restrict__ out)
{
    int tid = blockIdx.x * blockDim.x + threadIdx.x;
    if (tid < EC_SLOTS) g_s2t[tid] = -1;
    float4* o4 = (float4*)out;
    const int n4 = (N_TOK * M_DIM) / 4;
    const int stride = gridDim.x * blockDim.x;
    for (int i = tid; i < n4; i += stride)
        o4[i] = make_float4(0.f, 0.f, 0.f, 0.f);
}

// ---------------------------------------------------------------------------
// gate: exact fp32 routing
// ---------------------------------------------------------------------------
__global__ __launch_bounds__(256) void gate_kernel(
    const float* __restrict__ x, const float* __restrict__ wg)
{
    __shared__ float sx[M_DIM];
    __shared__ float slog[E_NUM];

    const int tok = blockIdx.x;
    const int tid = threadIdx.x;

    const float4* xr = (const float4*)(x + (size_t)tok * M_DIM);
    float4* sx4 = (float4*)sx;
    for (int i = tid; i < M_DIM / 4; i += 256) sx4[i] = xr[i];
    __syncthreads();

    const int wid = tid >> 5, lane = tid & 31;
    const float* __restrict__ w = wg + wid * M_DIM;
    float sum = 0.f;
    for (int m = lane; m < M_DIM; m += 32) sum = fmaf(sx[m], w[m], sum);
#pragma unroll
    for (int o = 16; o; o >>= 1) sum += __shfl_xor_sync(0xffffffffu, sum, o);
    if (lane == 0) slog[wid] = sum;
    __syncthreads();

    if (tid == 0) {
        float mx = slog[0]; int am = 0;
#pragma unroll
        for (int e = 1; e < E_NUM; ++e)
            if (slog[e] > mx) { mx = slog[e]; am = e; }
        float ge[E_NUM], den = 0.f;
#pragma unroll
        for (int e = 0; e < E_NUM; ++e) { ge[e] = expf(slog[e] - mx); den += ge[e]; }
        const float inv = 1.f / den;
#pragma unroll
        for (int e = 0; e < E_NUM; ++e) g_gates[tok * E_NUM + e] = ge[e] * inv;
        g_idx[tok]   = am;
        g_gate1[tok] = ge[am] * inv;
    }
}

// ---------------------------------------------------------------------------
// sched: exact cumsum capacity assignment + l_aux
// ---------------------------------------------------------------------------
__global__ __launch_bounds__(256) void sched_kernel(float* __restrict__ out,
                                                    int write_laux)
{
    __shared__ int   s_ce[E_NUM];
    __shared__ float s_me[E_NUM];

    const int tid = threadIdx.x;
    const int wid = tid >> 5, lane = tid & 31;

    int count = 0;
    for (int base = 0; base < N_TOK; base += 32) {
        const int tok = base + lane;
        const bool mine = (g_idx[tok] == wid);
        const unsigned bal = __ballot_sync(0xffffffffu, mine);
        if (mine) {
            const int loc = count + __popc(bal & ((1u << lane) - 1u));
            if (loc < C_CAP) g_s2t[wid * C_CAP + loc] = tok;
        }
        count += __popc(bal);
    }
    if (lane == 0) s_ce[wid] = count;

    float me = 0.f;
    for (int t = lane; t < N_TOK; t += 32) me += g_gates[t * E_NUM + wid];
#pragma unroll
    for (int o = 16; o; o >>= 1) me += __shfl_xor_sync(0xffffffffu, me, o);
    if (lane == 0) s_me[wid] = me;
    __syncthreads();

    if (tid == 0 && write_laux) {
        float acc = 0.f;
#pragma unroll
        for (int e = 0; e < E_NUM; ++e) acc += s_me[e] * (float)s_ce[e];
        out[(size_t)N_TOK * M_DIM] =
            acc * ((float)E_NUM / ((float)N_TOK * (float)N_TOK));
    }
}

// ---------------------------------------------------------------------------
// disp: gather token rows into slot order, split fp32 -> bf16 hi/lo
// ---------------------------------------------------------------------------
__global__ __launch_bounds__(256) void disp_kernel(const float* __restrict__ x)
{
    const int slot = blockIdx.x;
    const int t = g_s2t[slot];
    const float4* src = (t >= 0) ? (const float4*)(x + (size_t)t * M_DIM) : nullptr;
    __nv_bfloat16* dh = g_disp_hi + (size_t)slot * M_DIM;
    __nv_bfloat16* dl = g_disp_lo + (size_t)slot * M_DIM;
    for (int i = threadIdx.x; i < M_DIM / 4; i += 256) {
        float4 v = src ? src[i] : make_float4(0.f, 0.f, 0.f, 0.f);
        __nv_bfloat16 hh[4], ll[4];
        bsplit(v.x, hh[0], ll[0]); bsplit(v.y, hh[1], ll[1]);
        bsplit(v.z, hh[2], ll[2]); bsplit(v.w, hh[3], ll[3]);
        *(uint2*)(dh + i * 4) = *(uint2*)hh;
        *(uint2*)(dl + i * 4) = *(uint2*)ll;
    }
}

// ---------------------------------------------------------------------------
// weight transpose + split: src [E][R][C] fp32 -> dst [E][C][R] bf16 hi/lo
// ---------------------------------------------------------------------------
__global__ void wsplit_kernel(const float* __restrict__ src,
                              __nv_bfloat16* __restrict__ dhi,
                              __nv_bfloat16* __restrict__ dlo,
                              int R, int C)
{
    __shared__ float tile[32][33];
    const int e  = blockIdx.z;
    const int c0 = blockIdx.x * 32;
    const int r0 = blockIdx.y * 32;
    const int tx = threadIdx.x, ty = threadIdx.y;

    const float* s = src + (size_t)e * R * C;
#pragma unroll
    for (int i = 0; i < 4; ++i)
        tile[ty + 8 * i][tx] = s[(size_t)(r0 + ty + 8 * i) * C + c0 + tx];
    __syncthreads();

    __nv_bfloat16* dh = dhi + (size_t)e * C * R;
    __nv_bfloat16* dl = dlo + (size_t)e * C * R;
#pragma unroll
    for (int i = 0; i < 4; ++i) {
        const int c = c0 + ty + 8 * i;
        const int r = r0 + tx;
        __nv_bfloat16 hi, lo;
        bsplit(tile[tx][ty + 8 * i], hi, lo);
        dh[(size_t)c * R + r] = hi;
        dl[(size_t)c * R + r] = lo;
    }
}

// ---------------------------------------------------------------------------
// HMMA mainloop: acc += A @ B^T with 3-term bf16 split, 5-stage cp.async pipe
//   16 warps, warp grid 4m x 4n, warp tile 32x32, single barrier per chunk,
//   term-major MMA ordering (independent accumulators between term passes)
// ---------------------------------------------------------------------------
__device__ __forceinline__ void hmma_mainloop(
    const char* __restrict__ Ah, const char* __restrict__ Al,
    const char* __restrict__ Bh, const char* __restrict__ Bl,
    size_t pitch, int chunks, char* smem, float acc[2][4][4])
{
    const int tid  = threadIdx.x;
    const int wid  = tid >> 5, lane = tid & 31;
    const int wm   = (wid & 3) * 32;
    const int wn   = (wid >> 2) * 32;
    const uint32_t sbase = s2u(smem);

    // stage loader: 512 16B units per split, 1 cp16 per split per thread
    const int lrow = tid >> 2;               // 0..127
    const int lseg = tid & 3;                // 0..3 (16B segs of 64B row data)
    const uint32_t lso = lrow * ROW_STRIDE_B + lseg * 16;
    const size_t lgo_base = (size_t)lrow * pitch + lseg * 16;

    auto load_stage = [&](int st, int c) {
        const uint32_t sb = sbase + st * STAGE_B;
        const size_t go = lgo_base + (size_t)c * (KCHUNK * 2);
        cp16(sb + 0 * SPLIT_B + lso, Ah + go);
        cp16(sb + 1 * SPLIT_B + lso, Al + go);
        cp16(sb + 2 * SPLIT_B + lso, Bh + go);
        cp16(sb + 3 * SPLIT_B + lso, Bl + go);
        asm volatile("cp.async.commit_group;");
    };

#pragma unroll
    for (int s = 0; s < NSTAGE - 1; ++s) load_stage(s, s);

    const uint32_t aoff = (uint32_t)((wm + (lane & 15)) * ROW_STRIDE_B
                                     + ((lane >> 4) & 1) * 16);
    const uint32_t boff = (uint32_t)((wn + (lane & 7)) * ROW_STRIDE_B
                                     + ((lane >> 3) & 1) * 16);

    int buf = 0;
#pragma unroll 1
    for (int c = 0; c < chunks; ++c) {
        asm volatile("cp.async.wait_group %0;" :: "n"(NSTAGE - 2) : "memory");
        __syncthreads();

        if (c + NSTAGE - 1 < chunks)
            load_stage((c + NSTAGE - 1) % NSTAGE, c + NSTAGE - 1);

        const uint32_t sb = sbase + buf * STAGE_B;
#pragma unroll
        for (int ks = 0; ks < 2; ++ks) {
            const int kb2 = ks * 32;         // 16 elements * 2 bytes
            uint32_t ah[2][4], al[2][4], bh[4][2], bl[4][2];
#pragma unroll
            for (int mi = 0; mi < 2; ++mi) {
                const uint32_t ad = sb + aoff + kb2 + mi * 16 * ROW_STRIDE_B;
                ldsm4(ah[mi], ad);
                ldsm4(al[mi], ad + SPLIT_B);
            }
#pragma unroll
            for (int ni = 0; ni < 4; ++ni) {
                const uint32_t bd = sb + 2 * SPLIT_B + boff + kb2
                                    + ni * 8 * ROW_STRIDE_B;
                ldsm2(bh[ni], bd);
                ldsm2(bl[ni], bd + SPLIT_B);
            }
            // term-major: 8 independent accumulators per pass
#pragma unroll
            for (int mi = 0; mi < 2; ++mi)
#pragma unroll
                for (int ni = 0; ni < 4; ++ni)
                    mmabf16(acc[mi][ni], ah[mi], bh[ni]);
#pragma unroll
            for (int mi = 0; mi < 2; ++mi)
#pragma unroll
                for (int ni = 0; ni < 4; ++ni)
                    mmabf16(acc[mi][ni], al[mi], bh[ni]);
#pragma unroll
            for (int mi = 0; mi < 2; ++mi)
#pragma unroll
                for (int ni = 0; ni < 4; ++ni)
                    mmabf16(acc[mi][ni], ah[mi], bl[ni]);
        }
        buf = (buf + 1 == NSTAGE) ? 0 : buf + 1;
    }
}

// ---------------------------------------------------------------------------
// GEMM1: h[slot] = relu( disp[slot] @ w1[e]^T(cols) + b1[e] ) -> split hi/lo
// ---------------------------------------------------------------------------
__global__ __launch_bounds__(NTHREADS, 1) void gemm1_mma(const float* __restrict__ b1)
{
    extern __shared__ char smem[];
    const int tid = threadIdx.x;
    const int wid = tid >> 5, lane = tid & 31;
    const int row0 = blockIdx.y * 128;
    const int col0 = blockIdx.x * 128;
    const int e    = row0 >> 10;

    float acc[2][4][4];
#pragma unroll
    for (int mi = 0; mi < 2; ++mi)
#pragma unroll
        for (int ni = 0; ni < 4; ++ni)
#pragma unroll
            for (int k = 0; k < 4; ++k) acc[mi][ni][k] = 0.f;

    hmma_mainloop(
        (const char*)(g_disp_hi + (size_t)row0 * M_DIM),
        (const char*)(g_disp_lo + (size_t)row0 * M_DIM),
        (const char*)(g_w1t_hi + (size_t)e * H_DIM * M_DIM + (size_t)col0 * M_DIM),
        (const char*)(g_w1t_lo + (size_t)e * H_DIM * M_DIM + (size_t)col0 * M_DIM),
        (size_t)M_DIM * 2, M_DIM / KCHUNK, smem, acc);

    const int wm = (wid & 3) * 32;
    const int wn = (wid >> 2) * 32;
    const float* b1g = b1 + (size_t)e * H_DIM;

#pragma unroll
    for (int ni = 0; ni < 4; ++ni) {
        const int cg = col0 + wn + ni * 8 + (lane & 3) * 2;
        const float bv0 = b1g[cg], bv1 = b1g[cg + 1];
#pragma unroll
        for (int mi = 0; mi < 2; ++mi)
#pragma unroll
            for (int h = 0; h < 2; ++h) {
                const int rg = row0 + wm + mi * 16 + (lane >> 2) + h * 8;
                float v0 = fmaxf(acc[mi][ni][h * 2 + 0] + bv0, 0.f);
                float v1 = fmaxf(acc[mi][ni][h * 2 + 1] + bv1, 0.f);
                __nv_bfloat16 h0, l0, h1, l1;
                bsplit(v0, h0, l0);
                bsplit(v1, h1, l1);
                *(__nv_bfloat162*)(g_h_hi + (size_t)rg * H_DIM + cg) =
                    __nv_bfloat162(h0, h1);
                *(__nv_bfloat162*)(g_h_lo + (size_t)rg * H_DIM + cg) =
                    __nv_bfloat162(l0, l1);
            }
    }
}

// ---------------------------------------------------------------------------
// GEMM2: out[token(slot)] = gate1 * ( h[slot] @ w2[e]^T(cols) + b2[e] )
// ---------------------------------------------------------------------------
__global__ __launch_bounds__(NTHREADS, 1) void gemm2_mma(const float* __restrict__ b2,
                                                         float* __restrict__ out)
{
    extern __shared__ char smem[];
    const int tid = threadIdx.x;
    const int wid = tid >> 5, lane = tid & 31;
    const int row0 = blockIdx.y * 128;
    const int col0 = blockIdx.x * 128;
    const int e    = row0 >> 10;

    float acc[2][4][4];
#pragma unroll
    for (int mi = 0; mi < 2; ++mi)
#pragma unroll
        for (int ni = 0; ni < 4; ++ni)
#pragma unroll
            for (int k = 0; k < 4; ++k) acc[mi][ni][k] = 0.f;

    hmma_mainloop(
        (const char*)(g_h_hi + (size_t)row0 * H_DIM),
        (const char*)(g_h_lo + (size_t)row0 * H_DIM),
        (const char*)(g_w2t_hi + (size_t)e * M_DIM * H_DIM + (size_t)col0 * H_DIM),
        (const char*)(g_w2t_lo + (size_t)e * M_DIM * H_DIM + (size_t)col0 * H_DIM),
        (size_t)H_DIM * 2, H_DIM / KCHUNK, smem, acc);

    const int wm = (wid & 3) * 32;
    const int wn = (wid >> 2) * 32;
    const float* b2g = b2 + (size_t)e * M_DIM;

#pragma unroll
    for (int ni = 0; ni < 4; ++ni) {
        const int cg = col0 + wn + ni * 8 + (lane & 3) * 2;
        const float bv0 = b2g[cg], bv1 = b2g[cg + 1];
#pragma unroll
        for (int mi = 0; mi < 2; ++mi)
#pragma unroll
            for (int h = 0; h < 2; ++h) {
                const int rg = row0 + wm + mi * 16 + (lane >> 2) + h * 8;
                const int t = g_s2t[rg];
                if (t < 0) continue;
                const float g = g_gate1[t];
                float2 v;
                v.x = (acc[mi][ni][h * 2 + 0] + bv0) * g;
                v.y = (acc[mi][ni][h * 2 + 1] + bv1) * g;
                *(float2*)(out + (size_t)t * M_DIM + cg) = v;
            }
    }
}

// ---------------------------------------------------------------------------
// launch
// ---------------------------------------------------------------------------
extern "C" void kernel_launch(void* const* d_in, const int* in_sizes, int n_in,
                              void* d_out, int out_size)
{
    const float* x  = (const float*)d_in[0];
    const float* wg = (const float*)d_in[1];
    const float* w1 = (const float*)d_in[2];
    const float* b1 = (const float*)d_in[3];
    const float* w2 = (const float*)d_in[4];
    const float* b2 = (const float*)d_in[5];
    float* out = (float*)d_out;

    cudaFuncSetAttribute(gemm1_mma, cudaFuncAttributeMaxDynamicSharedMemorySize,
                         SMEM_BYTES);
    cudaFuncSetAttribute(gemm2_mma, cudaFuncAttributeMaxDynamicSharedMemorySize,
                         SMEM_BYTES);

    __nv_bfloat16 *w1t_hi, *w1t_lo, *w2t_hi, *w2t_lo;
    cudaGetSymbolAddress((void**)&w1t_hi, g_w1t_hi);
    cudaGetSymbolAddress((void**)&w1t_lo, g_w1t_lo);
    cudaGetSymbolAddress((void**)&w2t_hi, g_w2t_hi);
    cudaGetSymbolAddress((void**)&w2t_lo, g_w2t_lo);

    init_kernel<<<256, 256>>>(out);

    wsplit_kernel<<<dim3(H_DIM / 32, M_DIM / 32, E_NUM), dim3(32, 8)>>>(
        w1, w1t_hi, w1t_lo, M_DIM, H_DIM);
    wsplit_kernel<<<dim3(M_DIM / 32, H_DIM / 32, E_NUM), dim3(32, 8)>>>(
        w2, w2t_hi, w2t_lo, H_DIM, M_DIM);

    gate_kernel<<<N_TOK, 256>>>(x, wg);
    sched_kernel<<<1, 256>>>(out, (out_size > N_TOK * M_DIM) ? 1 : 0);
    disp_kernel<<<EC_SLOTS, 256>>>(x);

    gemm1_mma<<<dim3(H_DIM / 128, EC_SLOTS / 128), NTHREADS, SMEM_BYTES>>>(b1);
    gemm2_mma<<<dim3(M_DIM / 128, EC_SLOTS / 128), NTHREADS, SMEM_BYTES>>>(b2, out);
}